// round 3
// baseline (speedup 1.0000x reference)
#include <cuda_runtime.h>
#include <math.h>

#define NN 50000
#define EE 800000
#define OO 64
#define IN_DIM 192
#define OUT_DIM 128
#define EPS 1e-5f

// ---- scratch (static device globals; no runtime allocation) ----
__device__ float g_h[(size_t)EE * OUT_DIM];      // 409.6 MB edge GEMM output
__device__ float g_agg[NN * OO];                 // 12.8 MB aggregated messages
__device__ float g_sums[OUT_DIM];
__device__ float g_sumsq[OUT_DIM];
__device__ float g_scale1[OUT_DIM];
__device__ float g_shift1[OUT_DIM];
__device__ float g_s2[OO], g_q2[OO];
__device__ float g_scale2[OO], g_shift2[OO];

__device__ __forceinline__ float softplus_f(float x) {
    return fmaxf(x, 0.f) + log1pf(expf(-fabsf(x)));
}

// ---------------------------------------------------------------
// K0: zero accumulators
// ---------------------------------------------------------------
__global__ void zero_kernel() {
    int idx = blockIdx.x * blockDim.x + threadIdx.x;
    if (idx < NN * OO) g_agg[idx] = 0.f;
    if (idx < OUT_DIM) { g_sums[idx] = 0.f; g_sumsq[idx] = 0.f; }
    if (idx < OO)      { g_s2[idx] = 0.f;   g_q2[idx] = 0.f; }
}

// ---------------------------------------------------------------
// K1: h = cat(n_feat[dst], n_feat[src], e_feat) @ W^T + b
//     tile: 128 edges x 128 out cols, K=192 in 12 chunks of 16.
//     Also accumulates per-column sum and sum-of-squares for BN1.
// ---------------------------------------------------------------
__global__ __launch_bounds__(256, 2)
void gemm_kernel(const float* __restrict__ n_feat,
                 const float* __restrict__ e_feat,
                 const int*   __restrict__ src,
                 const int*   __restrict__ dst,
                 const float* __restrict__ W,
                 const float* __restrict__ bias) {
    __shared__ float As[16][132];     // [k][m], padded
    __shared__ float Bs[16][132];     // [k][n], padded
    __shared__ int   sdst[128], ssrc[128];
    __shared__ float sred[128][17];

    const int t  = threadIdx.x;
    const int tx = t & 15;            // out-col group
    const int ty = t >> 4;            // edge group
    const int e0 = blockIdx.x * 128;

    if (t < 128) { sdst[t] = dst[e0 + t]; ssrc[t] = src[e0 + t]; }
    __syncthreads();

    float acc[8][8];
#pragma unroll
    for (int i = 0; i < 8; i++)
#pragma unroll
        for (int j = 0; j < 8; j++) acc[i][j] = 0.f;

#pragma unroll 1
    for (int kc = 0; kc < 12; kc++) {
        const int k0 = kc * 16;
        // load A (gathered concat) and W chunk: 2 float4 each per thread
#pragma unroll
        for (int q = 0; q < 2; q++) {
            int p4 = t * 2 + q;           // 0..511
            int m  = p4 >> 2;             // row 0..127
            int kk = (p4 & 3) * 4;        // 0,4,8,12
            int kg = k0 + kk;
            const float* ap;
            if (kg < 64)        ap = n_feat + (size_t)sdst[m] * 64 + kg;
            else if (kg < 128)  ap = n_feat + (size_t)ssrc[m] * 64 + (kg - 64);
            else                ap = e_feat + (size_t)(e0 + m) * 64 + (kg - 128);
            float4 v = *(const float4*)ap;
            As[kk + 0][m] = v.x; As[kk + 1][m] = v.y;
            As[kk + 2][m] = v.z; As[kk + 3][m] = v.w;

            float4 w = *(const float4*)(W + (size_t)m * IN_DIM + k0 + kk);
            Bs[kk + 0][m] = w.x; Bs[kk + 1][m] = w.y;
            Bs[kk + 2][m] = w.z; Bs[kk + 3][m] = w.w;
        }
        __syncthreads();

#pragma unroll
        for (int kk = 0; kk < 16; kk++) {
            float a[8], bb[8];
            *(float4*)&a[0]  = *(float4*)&As[kk][ty * 8];
            *(float4*)&a[4]  = *(float4*)&As[kk][ty * 8 + 4];
            *(float4*)&bb[0] = *(float4*)&Bs[kk][tx * 8];
            *(float4*)&bb[4] = *(float4*)&Bs[kk][tx * 8 + 4];
#pragma unroll
            for (int i = 0; i < 8; i++)
#pragma unroll
                for (int j = 0; j < 8; j++)
                    acc[i][j] = fmaf(a[i], bb[j], acc[i][j]);
        }
        __syncthreads();
    }

    // epilogue: bias, store h, column partial sums
    float bj[8];
    *(float4*)&bj[0] = *(const float4*)(bias + tx * 8);
    *(float4*)&bj[4] = *(const float4*)(bias + tx * 8 + 4);

    float cs[8], cq[8];
#pragma unroll
    for (int j = 0; j < 8; j++) { cs[j] = 0.f; cq[j] = 0.f; }

#pragma unroll
    for (int i = 0; i < 8; i++) {
        int e = e0 + ty * 8 + i;
        float hv[8];
#pragma unroll
        for (int j = 0; j < 8; j++) {
            float v = acc[i][j] + bj[j];
            hv[j] = v;
            cs[j] += v;
            cq[j] = fmaf(v, v, cq[j]);
        }
        float* hp = g_h + (size_t)e * OUT_DIM + tx * 8;
        *(float4*)hp       = make_float4(hv[0], hv[1], hv[2], hv[3]);
        *(float4*)(hp + 4) = make_float4(hv[4], hv[5], hv[6], hv[7]);
    }

    // reduce per-column partials across ty and atomically accumulate
#pragma unroll
    for (int j = 0; j < 8; j++) sred[tx * 8 + j][ty] = cs[j];
    __syncthreads();
    if (t < 128) {
        float s = 0.f;
#pragma unroll
        for (int k = 0; k < 16; k++) s += sred[t][k];
        atomicAdd(&g_sums[t], s);
    }
    __syncthreads();
#pragma unroll
    for (int j = 0; j < 8; j++) sred[tx * 8 + j][ty] = cq[j];
    __syncthreads();
    if (t < 128) {
        float s = 0.f;
#pragma unroll
        for (int k = 0; k < 16; k++) s += sred[t][k];
        atomicAdd(&g_sumsq[t], s);
    }
}

// ---------------------------------------------------------------
// K2: BN1 stats -> per-column scale/shift
// ---------------------------------------------------------------
__global__ void finalize1_kernel(const float* __restrict__ g1,
                                 const float* __restrict__ beta1) {
    int c = threadIdx.x;
    if (c >= OUT_DIM) return;
    float mean = g_sums[c] / (float)EE;
    float var  = g_sumsq[c] / (float)EE - mean * mean;
    float rstd = rsqrtf(var + EPS);
    float sc = rstd * g1[c];
    g_scale1[c] = sc;
    g_shift1[c] = beta1[c] - mean * sc;
}

// ---------------------------------------------------------------
// K3: BN1 apply + sigmoid*softplus gate + vectorized atomic scatter
//     one thread = one edge x 4 columns; red.global.add.v4.f32
// ---------------------------------------------------------------
__global__ __launch_bounds__(256)
void act_scatter_kernel(const int* __restrict__ dst) {
    int idx = blockIdx.x * blockDim.x + threadIdx.x;   // over EE*16
    int e  = idx >> 4;
    int cg = (idx & 15) * 4;                            // column group 0,4,...,60
    const float* hp = g_h + (size_t)e * OUT_DIM;
    float4 f4 = *(const float4*)(hp + cg);
    float4 g4 = *(const float4*)(hp + cg + 64);
    float4 s1 = *(const float4*)(g_scale1 + cg);
    float4 h1 = *(const float4*)(g_shift1 + cg);
    float4 s2 = *(const float4*)(g_scale1 + cg + 64);
    float4 h2 = *(const float4*)(g_shift1 + cg + 64);

    float m0, m1, m2, m3;
    {
        float f = f4.x * s1.x + h1.x, g = g4.x * s2.x + h2.x;
        m0 = (1.f / (1.f + expf(-f))) * softplus_f(g);
        f = f4.y * s1.y + h1.y; g = g4.y * s2.y + h2.y;
        m1 = (1.f / (1.f + expf(-f))) * softplus_f(g);
        f = f4.z * s1.z + h1.z; g = g4.z * s2.z + h2.z;
        m2 = (1.f / (1.f + expf(-f))) * softplus_f(g);
        f = f4.w * s1.w + h1.w; g = g4.w * s2.w + h2.w;
        m3 = (1.f / (1.f + expf(-f))) * softplus_f(g);
    }
    float* ap = g_agg + (size_t)dst[e] * 64 + cg;
    asm volatile("red.global.add.v4.f32 [%0], {%1,%2,%3,%4};"
                 :: "l"(ap), "f"(m0), "f"(m1), "f"(m2), "f"(m3) : "memory");
}

// ---------------------------------------------------------------
// K4: BN2 stats over agg (per-column over N rows)
// ---------------------------------------------------------------
__global__ void agg_stats_kernel() {
    __shared__ float sh[4][64], shq[4][64];
    int c  = threadIdx.x & 63;
    int rg = threadIdx.x >> 6;            // 0..3
    int r0 = blockIdx.x * 250;            // 200 blocks * 250 rows = 50000
    float s = 0.f, q = 0.f;
    for (int r = r0 + rg; r < r0 + 250; r += 4) {
        float v = g_agg[r * 64 + c];
        s += v;
        q = fmaf(v, v, q);
    }
    sh[rg][c] = s; shq[rg][c] = q;
    __syncthreads();
    if (threadIdx.x < 64) {
        float ss = sh[0][c] + sh[1][c] + sh[2][c] + sh[3][c];
        float qq = shq[0][c] + shq[1][c] + shq[2][c] + shq[3][c];
        atomicAdd(&g_s2[c], ss);
        atomicAdd(&g_q2[c], qq);
    }
}

__global__ void finalize2_kernel(const float* __restrict__ g2,
                                 const float* __restrict__ beta2) {
    int c = threadIdx.x;
    if (c >= OO) return;
    float mean = g_s2[c] / (float)NN;
    float var  = g_q2[c] / (float)NN - mean * mean;
    float rstd = rsqrtf(var + EPS);
    float sc = rstd * g2[c];
    g_scale2[c] = sc;
    g_shift2[c] = beta2[c] - mean * sc;
}

// ---------------------------------------------------------------
// K6: out = softplus(BN2(agg) + n_feat)
// ---------------------------------------------------------------
__global__ void output_kernel(const float* __restrict__ n_feat,
                              float* __restrict__ out) {
    int idx = blockIdx.x * blockDim.x + threadIdx.x;
    if (idx >= NN * OO) return;
    int c = idx & 63;
    float v = g_agg[idx] * g_scale2[c] + g_shift2[c] + n_feat[idx];
    out[idx] = softplus_f(v);
}

// ---------------------------------------------------------------
extern "C" void kernel_launch(void* const* d_in, const int* in_sizes, int n_in,
                              void* d_out, int out_size) {
    const float* n_feat = (const float*)d_in[0];
    const float* e_feat = (const float*)d_in[1];
    const int*   src    = (const int*)  d_in[2];
    const int*   dst    = (const int*)  d_in[3];
    const float* W      = (const float*)d_in[4];
    const float* b      = (const float*)d_in[5];
    const float* g1     = (const float*)d_in[6];
    const float* beta1  = (const float*)d_in[7];
    const float* g2     = (const float*)d_in[8];
    const float* beta2  = (const float*)d_in[9];
    float* out = (float*)d_out;

    zero_kernel<<<(NN * OO + 255) / 256, 256>>>();
    gemm_kernel<<<EE / 128, 256>>>(n_feat, e_feat, src, dst, W, b);
    finalize1_kernel<<<1, 128>>>(g1, beta1);
    act_scatter_kernel<<<(EE * 16) / 256, 256>>>(dst);
    agg_stats_kernel<<<200, 256>>>();
    finalize2_kernel<<<1, 64>>>(g2, beta2);
    output_kernel<<<(NN * OO + 255) / 256, 256>>>(n_feat, out);
}

// round 6
// speedup vs baseline: 1.4542x; 1.4542x over previous
#include <cuda_runtime.h>
#include <cuda_bf16.h>
#include <math.h>
#include <stdint.h>

#define NN 50000
#define EE 800000
#define OO 64
#define IN_DIM 192
#define OUT_DIM 128
#define EPS 1e-5f
#define NTILES (EE / 128)

// ---- static device scratch (no runtime allocation) ----
__device__ float g_Pd[(size_t)NN * 128];   // n_feat @ W_d^T + b   (25.6 MB)
__device__ float g_Ps[(size_t)NN * 128];   // n_feat @ W_s^T       (25.6 MB)
__device__ float g_agg[NN * OO];
__device__ float g_sums[OUT_DIM], g_sumsq[OUT_DIM];
__device__ float g_scale1[OUT_DIM], g_shift1[OUT_DIM];
__device__ float g_s2[OO], g_q2[OO], g_scale2[OO], g_shift2[OO];

__device__ __forceinline__ float softplus_f(float x) {
    return fmaxf(x, 0.f) + log1pf(expf(-fabsf(x)));
}

__device__ __forceinline__ uint32_t s2u(const void* p) {
    uint32_t a;
    asm("{ .reg .u64 t; cvta.to.shared.u64 t, %1; cvt.u32.u64 %0, t; }" : "=r"(a) : "l"(p));
    return a;
}

#define SWZ(o) ((o) ^ ((((uint32_t)(o)) >> 3) & 0x70))

// dynamic smem layout (bytes)
#define SM_SC    0
#define SM_SH    512
#define SM_AHI   1024
#define SM_ALO   17408
#define SM_BHI   33792
#define SM_BLO   50176
#define SM_TOTAL 66560

// pack two floats -> bf16x2 hi word + lo (residual) word
__device__ __forceinline__ void split2(float x, float y, uint32_t& hi, uint32_t& lo) {
    __nv_bfloat16 hx = __float2bfloat16(x), hy = __float2bfloat16(y);
    __nv_bfloat16 lx = __float2bfloat16(x - __bfloat162float(hx));
    __nv_bfloat16 ly = __float2bfloat16(y - __bfloat162float(hy));
    hi = ((uint32_t)__bfloat16_as_ushort(hy) << 16) | __bfloat16_as_ushort(hx);
    lo = ((uint32_t)__bfloat16_as_ushort(ly) << 16) | __bfloat16_as_ushort(lx);
}

// ---------------- warp MMA primitives (compute_80-legal) ----------------
__device__ __forceinline__ void ldmx4(uint32_t a, uint32_t* r) {
    asm volatile("ldmatrix.sync.aligned.m8n8.x4.shared.b16 {%0,%1,%2,%3}, [%4];"
        : "=r"(r[0]), "=r"(r[1]), "=r"(r[2]), "=r"(r[3]) : "r"(a));
}
__device__ __forceinline__ void mma16816(float* c, const uint32_t* a, uint32_t b0, uint32_t b1) {
    asm volatile("mma.sync.aligned.m16n8k16.row.col.f32.bf16.bf16.f32 "
        "{%0,%1,%2,%3}, {%4,%5,%6,%7}, {%8,%9}, {%0,%1,%2,%3};"
        : "+f"(c[0]), "+f"(c[1]), "+f"(c[2]), "+f"(c[3])
        : "r"(a[0]), "r"(a[1]), "r"(a[2]), "r"(a[3]), "r"(b0), "r"(b1));
}
// A-operand ldmatrix address: rows r0..r0+15, k chunk k0..k0+15 (SW128 layout, 128B rows)
__device__ __forceinline__ uint32_t a_addr(uint32_t base, int lane, int r0, int k0) {
    int row = r0 + (lane & 15);
    int chunk = (k0 >> 3) + ((lane >> 4) & 1);
    return base + SWZ(row * 128 + chunk * 16);
}
// B-operand: two ntiles j0..j0+7, j0+8..j0+15 at kstep k0 (mats {j,c},{j,c+1},{j+8,c},{j+8,c+1})
__device__ __forceinline__ uint32_t b_addr(uint32_t base, int lane, int j0, int k0) {
    int row = j0 + (lane & 7) + ((lane & 16) ? 8 : 0);
    int chunk = (k0 >> 3) + ((lane >> 3) & 1);
    return base + SWZ(row * 128 + chunk * 16);
}

// ---------------------------------------------------------------
// K0: zero accumulators
// ---------------------------------------------------------------
__global__ void zero_kernel() {
    int idx = blockIdx.x * blockDim.x + threadIdx.x;
    if (idx < NN * OO) g_agg[idx] = 0.f;
    if (idx < OUT_DIM) { g_sums[idx] = 0.f; g_sumsq[idx] = 0.f; }
    if (idx < OO)      { g_s2[idx] = 0.f;   g_q2[idx] = 0.f; }
}

// ---------------------------------------------------------------
// K_pre: P_d[n][j] = b[j] + n_feat[n]·W[j,0:64]
//        P_s[n][j] =        n_feat[n]·W[j,64:128]
// ---------------------------------------------------------------
__global__ __launch_bounds__(256)
void pre_kernel(const float* __restrict__ n_feat,
                const float* __restrict__ W,
                const float* __restrict__ b) {
    __shared__ float4 sn[16];
    const int t = threadIdx.x;
    const int j = t & 127, tab = t >> 7;

    float wreg[64];
    const float* wrow = W + (size_t)j * IN_DIM + tab * 64;
#pragma unroll
    for (int q = 0; q < 16; q++) {
        float4 v = *(const float4*)(wrow + q * 4);
        wreg[q * 4 + 0] = v.x; wreg[q * 4 + 1] = v.y;
        wreg[q * 4 + 2] = v.z; wreg[q * 4 + 3] = v.w;
    }
    const float bj = (tab == 0) ? __ldg(b + j) : 0.f;
    float* outT = (tab == 0) ? g_Pd : g_Ps;

    for (int n = blockIdx.x; n < NN; n += gridDim.x) {
        __syncthreads();
        if (t < 16) sn[t] = *(const float4*)(n_feat + (size_t)n * 64 + t * 4);
        __syncthreads();
        float acc = bj;
#pragma unroll
        for (int q = 0; q < 16; q++) {
            float4 v = sn[q];
            acc = fmaf(v.x, wreg[q * 4 + 0], acc);
            acc = fmaf(v.y, wreg[q * 4 + 1], acc);
            acc = fmaf(v.z, wreg[q * 4 + 2], acc);
            acc = fmaf(v.w, wreg[q * 4 + 3], acc);
        }
        outT[(size_t)n * 128 + j] = acc;
    }
}

// ---------------------------------------------------------------
// smem tile loaders (bf16 hi/lo split, SW128-swizzled, 128B rows)
// ---------------------------------------------------------------
__device__ __forceinline__ void load_w_tiles(char* smem, const float* __restrict__ W, int tid) {
    for (int idx = tid; idx < 4096; idx += 512) {
        int j = idx >> 5, cp = idx & 31;
        float2 v = *(const float2*)(W + (size_t)j * IN_DIM + 128 + cp * 2);
        uint32_t hi, lo; split2(v.x, v.y, hi, lo);
        uint32_t off = SWZ(j * 128 + cp * 4);
        *(uint32_t*)(smem + SM_BHI + off) = hi;
        *(uint32_t*)(smem + SM_BLO + off) = lo;
    }
}
__device__ __forceinline__ void load_e_tile(char* smem, const float* __restrict__ e_feat,
                                            int e0, int tid) {
    for (int idx = tid; idx < 4096; idx += 512) {
        int r = idx >> 5, cp = idx & 31;
        float2 v = *(const float2*)(e_feat + (size_t)(e0 + r) * 64 + cp * 2);
        uint32_t hi, lo; split2(v.x, v.y, hi, lo);
        uint32_t off = SWZ(r * 128 + cp * 4);
        *(uint32_t*)(smem + SM_AHI + off) = hi;
        *(uint32_t*)(smem + SM_ALO + off) = lo;
    }
}

// tile GEMM core: computes 8 ntile accumulators (4 "filt-half", 4 "core-half")
__device__ __forceinline__ void tile_mma(uint32_t sb, int lane, int m0, int cg, float* acc) {
#pragma unroll
    for (int k0 = 0; k0 < 64; k0 += 16) {
        uint32_t ah[4], al[4];
        ldmx4(a_addr(sb + SM_AHI, lane, m0, k0), ah);
        ldmx4(a_addr(sb + SM_ALO, lane, m0, k0), al);
#pragma unroll
        for (int half = 0; half < 2; half++) {
#pragma unroll
            for (int np = 0; np < 2; np++) {
                int j0 = half * 64 + cg * 32 + np * 16;
                uint32_t bh[4], bl[4];
                ldmx4(b_addr(sb + SM_BHI, lane, j0, k0), bh);
                ldmx4(b_addr(sb + SM_BLO, lane, j0, k0), bl);
                float* c0 = acc + (half * 4 + np * 2) * 4;
                float* c1 = c0 + 4;
                mma16816(c0, ah, bh[0], bh[1]);
                mma16816(c1, ah, bh[2], bh[3]);
                mma16816(c0, al, bh[0], bh[1]);
                mma16816(c1, al, bh[2], bh[3]);
                mma16816(c0, ah, bl[0], bl[1]);
                mma16816(c1, ah, bl[2], bl[3]);
            }
        }
    }
}

// ---------------------------------------------------------------
// pass1: per-edge h -> column sum/sumsq (BN1 stats)
// ---------------------------------------------------------------
__global__ __launch_bounds__(512, 1)
void pass1_kernel(const float* __restrict__ e_feat,
                  const int* __restrict__ src, const int* __restrict__ dst,
                  const float* __restrict__ W) {
    extern __shared__ char smem[];
    const uint32_t sb = s2u(smem);
    const int tid = threadIdx.x, wid = tid >> 5, lane = tid & 31;
    const int m0 = (wid & 7) * 16, cg = wid >> 3;
    const int g = lane >> 2, t = lane & 3;

    load_w_tiles(smem, W, tid);
    __syncthreads();

    float cs[16], cq[16];
#pragma unroll
    for (int k = 0; k < 16; k++) { cs[k] = 0.f; cq[k] = 0.f; }

    for (int tile = blockIdx.x; tile < NTILES; tile += gridDim.x) {
        const int e0 = tile * 128;
        __syncthreads();
        load_e_tile(smem, e_feat, e0, tid);
        __syncthreads();

        float acc[32];
#pragma unroll
        for (int k = 0; k < 32; k++) acc[k] = 0.f;
        tile_mma(sb, lane, m0, cg, acc);

        const int e1 = e0 + m0 + g, e2 = e1 + 8;
        const int d1 = __ldg(dst + e1), s1 = __ldg(src + e1);
        const int d2 = __ldg(dst + e2), s2 = __ldg(src + e2);
        const float* Pd1 = g_Pd + (size_t)d1 * 128;
        const float* Ps1 = g_Ps + (size_t)s1 * 128;
        const float* Pd2 = g_Pd + (size_t)d2 * 128;
        const float* Ps2 = g_Ps + (size_t)s2 * 128;
#pragma unroll
        for (int slot = 0; slot < 8; slot++) {
            int col = (slot >> 2) * 64 + cg * 32 + (slot & 3) * 8 + t * 2;
            float2 pa = __ldg((const float2*)(Pd1 + col));
            float2 pb = __ldg((const float2*)(Ps1 + col));
            float2 pc = __ldg((const float2*)(Pd2 + col));
            float2 pd = __ldg((const float2*)(Ps2 + col));
            float h0 = acc[slot * 4 + 0] + pa.x + pb.x;
            float h1 = acc[slot * 4 + 1] + pa.y + pb.y;
            float h2 = acc[slot * 4 + 2] + pc.x + pd.x;
            float h3 = acc[slot * 4 + 3] + pc.y + pd.y;
            cs[slot * 2 + 0] += h0 + h2;
            cs[slot * 2 + 1] += h1 + h3;
            cq[slot * 2 + 0] += h0 * h0 + h2 * h2;
            cq[slot * 2 + 1] += h1 * h1 + h3 * h3;
        }
    }

    // reduce over g (lanes differing in bits 2..4), then RED per column
#pragma unroll
    for (int k = 0; k < 16; k++) {
#pragma unroll
        for (int m = 4; m < 32; m <<= 1) {
            cs[k] += __shfl_xor_sync(0xffffffffu, cs[k], m);
            cq[k] += __shfl_xor_sync(0xffffffffu, cq[k], m);
        }
    }
    if (lane < 4) {
#pragma unroll
        for (int slot = 0; slot < 8; slot++) {
            int col = (slot >> 2) * 64 + cg * 32 + (slot & 3) * 8 + lane * 2;
            asm volatile("red.global.add.v2.f32 [%0], {%1,%2};"
                :: "l"(g_sums + col), "f"(cs[slot * 2]), "f"(cs[slot * 2 + 1]) : "memory");
            asm volatile("red.global.add.v2.f32 [%0], {%1,%2};"
                :: "l"(g_sumsq + col), "f"(cq[slot * 2]), "f"(cq[slot * 2 + 1]) : "memory");
        }
    }
}

// ---------------------------------------------------------------
// finalize1: BN1 scale/shift
// ---------------------------------------------------------------
__global__ void finalize1_kernel(const float* __restrict__ g1,
                                 const float* __restrict__ beta1) {
    int c = threadIdx.x;
    if (c >= OUT_DIM) return;
    float mean = g_sums[c] / (float)EE;
    float var  = g_sumsq[c] / (float)EE - mean * mean;
    float sc = rsqrtf(var + EPS) * g1[c];
    g_scale1[c] = sc;
    g_shift1[c] = beta1[c] - mean * sc;
}

// ---------------------------------------------------------------
// pass2: h -> BN1 -> sigmoid*softplus -> RED scatter into g_agg
// ---------------------------------------------------------------
__global__ __launch_bounds__(512, 1)
void pass2_kernel(const float* __restrict__ e_feat,
                  const int* __restrict__ src, const int* __restrict__ dst,
                  const float* __restrict__ W) {
    extern __shared__ char smem[];
    const uint32_t sb = s2u(smem);
    const int tid = threadIdx.x, wid = tid >> 5, lane = tid & 31;
    const int m0 = (wid & 7) * 16, cg = wid >> 3;
    const int g = lane >> 2, t = lane & 3;

    load_w_tiles(smem, W, tid);
    if (tid < 128) {
        ((float*)(smem + SM_SC))[tid] = g_scale1[tid];
        ((float*)(smem + SM_SH))[tid] = g_shift1[tid];
    }
    __syncthreads();
    const float* sSc = (const float*)(smem + SM_SC);
    const float* sSh = (const float*)(smem + SM_SH);

    for (int tile = blockIdx.x; tile < NTILES; tile += gridDim.x) {
        const int e0 = tile * 128;
        __syncthreads();
        load_e_tile(smem, e_feat, e0, tid);
        __syncthreads();

        float acc[32];
#pragma unroll
        for (int k = 0; k < 32; k++) acc[k] = 0.f;
        tile_mma(sb, lane, m0, cg, acc);

        const int e1 = e0 + m0 + g, e2 = e1 + 8;
        const int d1 = __ldg(dst + e1), s1 = __ldg(src + e1);
        const int d2 = __ldg(dst + e2), s2 = __ldg(src + e2);
        const float* Pd1 = g_Pd + (size_t)d1 * 128;
        const float* Ps1 = g_Ps + (size_t)s1 * 128;
        const float* Pd2 = g_Pd + (size_t)d2 * 128;
        const float* Ps2 = g_Ps + (size_t)s2 * 128;
        float* a1 = g_agg + (size_t)d1 * 64;
        float* a2 = g_agg + (size_t)d2 * 64;

#pragma unroll
        for (int nt = 0; nt < 4; nt++) {
            int cf = cg * 32 + nt * 8 + t * 2;   // filt col in [0,64)
            int cc = cf + 64;                    // core col
            float sc_f0 = sSc[cf], sh_f0 = sSh[cf], sc_f1 = sSc[cf + 1], sh_f1 = sSh[cf + 1];
            float sc_c0 = sSc[cc], sh_c0 = sSh[cc], sc_c1 = sSc[cc + 1], sh_c1 = sSh[cc + 1];
            const float* af = acc + nt * 4;        // filt slots
            const float* ac = acc + (4 + nt) * 4;  // core slots

            // row g
            {
                float2 pf1 = __ldg((const float2*)(Pd1 + cf));
                float2 qf1 = __ldg((const float2*)(Ps1 + cf));
                float2 pc1 = __ldg((const float2*)(Pd1 + cc));
                float2 qc1 = __ldg((const float2*)(Ps1 + cc));
                float f0 = (af[0] + pf1.x + qf1.x) * sc_f0 + sh_f0;
                float f1 = (af[1] + pf1.y + qf1.y) * sc_f1 + sh_f1;
                float c0 = (ac[0] + pc1.x + qc1.x) * sc_c0 + sh_c0;
                float c1 = (ac[1] + pc1.y + qc1.y) * sc_c1 + sh_c1;
                float v0 = (1.f / (1.f + expf(-f0))) * softplus_f(c0);
                float v1 = (1.f / (1.f + expf(-f1))) * softplus_f(c1);
                asm volatile("red.global.add.v2.f32 [%0], {%1,%2};"
                    :: "l"(a1 + cf), "f"(v0), "f"(v1) : "memory");
            }
            // row g+8
            {
                float2 pf2 = __ldg((const float2*)(Pd2 + cf));
                float2 qf2 = __ldg((const float2*)(Ps2 + cf));
                float2 pc2 = __ldg((const float2*)(Pd2 + cc));
                float2 qc2 = __ldg((const float2*)(Ps2 + cc));
                float f0 = (af[2] + pf2.x + qf2.x) * sc_f0 + sh_f0;
                float f1 = (af[3] + pf2.y + qf2.y) * sc_f1 + sh_f1;
                float c0 = (ac[2] + pc2.x + qc2.x) * sc_c0 + sh_c0;
                float c1 = (ac[3] + pc2.y + qc2.y) * sc_c1 + sh_c1;
                float v0 = (1.f / (1.f + expf(-f0))) * softplus_f(c0);
                float v1 = (1.f / (1.f + expf(-f1))) * softplus_f(c1);
                asm volatile("red.global.add.v2.f32 [%0], {%1,%2};"
                    :: "l"(a2 + cf), "f"(v0), "f"(v1) : "memory");
            }
        }
    }
}

// ---------------------------------------------------------------
// BN2 stats + finalize + output
// ---------------------------------------------------------------
__global__ void agg_stats_kernel() {
    __shared__ float sh[4][64], shq[4][64];
    int c  = threadIdx.x & 63;
    int rg = threadIdx.x >> 6;
    int r0 = blockIdx.x * 250;
    float s = 0.f, q = 0.f;
    for (int r = r0 + rg; r < r0 + 250; r += 4) {
        float v = g_agg[r * 64 + c];
        s += v;
        q = fmaf(v, v, q);
    }
    sh[rg][c] = s; shq[rg][c] = q;
    __syncthreads();
    if (threadIdx.x < 64) {
        atomicAdd(&g_s2[c], sh[0][c] + sh[1][c] + sh[2][c] + sh[3][c]);
        atomicAdd(&g_q2[c], shq[0][c] + shq[1][c] + shq[2][c] + shq[3][c]);
    }
}

__global__ void finalize2_kernel(const float* __restrict__ g2,
                                 const float* __restrict__ beta2) {
    int c = threadIdx.x;
    if (c >= OO) return;
    float mean = g_s2[c] / (float)NN;
    float var  = g_q2[c] / (float)NN - mean * mean;
    float sc = rsqrtf(var + EPS) * g2[c];
    g_scale2[c] = sc;
    g_shift2[c] = beta2[c] - mean * sc;
}

__global__ void output_kernel(const float* __restrict__ n_feat,
                              float* __restrict__ out) {
    int idx = blockIdx.x * blockDim.x + threadIdx.x;
    if (idx >= NN * OO) return;
    int c = idx & 63;
    float v = g_agg[idx] * g_scale2[c] + g_shift2[c] + n_feat[idx];
    out[idx] = softplus_f(v);
}

// ---------------------------------------------------------------
extern "C" void kernel_launch(void* const* d_in, const int* in_sizes, int n_in,
                              void* d_out, int out_size) {
    const float* n_feat = (const float*)d_in[0];
    const float* e_feat = (const float*)d_in[1];
    const int*   src    = (const int*)  d_in[2];
    const int*   dst    = (const int*)  d_in[3];
    const float* W      = (const float*)d_in[4];
    const float* b      = (const float*)d_in[5];
    const float* g1     = (const float*)d_in[6];
    const float* beta1  = (const float*)d_in[7];
    const float* g2     = (const float*)d_in[8];
    const float* beta2  = (const float*)d_in[9];
    float* out = (float*)d_out;

    cudaFuncSetAttribute(pass1_kernel, cudaFuncAttributeMaxDynamicSharedMemorySize, SM_TOTAL);
    cudaFuncSetAttribute(pass2_kernel, cudaFuncAttributeMaxDynamicSharedMemorySize, SM_TOTAL);

    zero_kernel<<<(NN * OO + 255) / 256, 256>>>();
    pre_kernel<<<444, 256>>>(n_feat, W, b);
    pass1_kernel<<<148, 512, SM_TOTAL>>>(e_feat, src, dst, W);
    finalize1_kernel<<<1, 128>>>(g1, beta1);
    pass2_kernel<<<148, 512, SM_TOTAL>>>(e_feat, src, dst, W);
    agg_stats_kernel<<<200, 256>>>();
    finalize2_kernel<<<1, 64>>>(g2, beta2);
    output_kernel<<<(NN * OO + 255) / 256, 256>>>(n_feat, out);
}

// round 7
// speedup vs baseline: 1.8870x; 1.2976x over previous
#include <cuda_runtime.h>
#include <cuda_bf16.h>
#include <math.h>
#include <stdint.h>

#define NN 50000
#define EE 800000
#define OO 64
#define IN_DIM 192
#define OUT_DIM 128
#define EPS 1e-5f
#define NTILES (EE / 128)

// ---- static device scratch (no runtime allocation) ----
__device__ float g_h[(size_t)EE * OUT_DIM];  // 409.6 MB edge GEMM output
__device__ float g_Pd[(size_t)NN * 128];     // n_feat @ W_d^T + b   (25.6 MB)
__device__ float g_Ps[(size_t)NN * 128];     // n_feat @ W_s^T       (25.6 MB)
__device__ float g_agg[NN * OO];
__device__ float g_sums[OUT_DIM], g_sumsq[OUT_DIM];
__device__ float g_scale1[OUT_DIM], g_shift1[OUT_DIM];
__device__ float g_s2[OO], g_q2[OO], g_scale2[OO], g_shift2[OO];

__device__ __forceinline__ float softplus_f(float x) {
    return fmaxf(x, 0.f) + log1pf(expf(-fabsf(x)));
}

__device__ __forceinline__ uint32_t s2u(const void* p) {
    uint32_t a;
    asm("{ .reg .u64 t; cvta.to.shared.u64 t, %1; cvt.u32.u64 %0, t; }" : "=r"(a) : "l"(p));
    return a;
}

#define SWZ(o) ((o) ^ ((((uint32_t)(o)) >> 3) & 0x70))

// dynamic smem layout (bytes)
#define SM_AHI   0
#define SM_ALO   16384
#define SM_BHI   32768
#define SM_BLO   49152
#define SM_TOTAL 65536

// pack two floats -> bf16x2 hi word + lo (residual) word
__device__ __forceinline__ void split2(float x, float y, uint32_t& hi, uint32_t& lo) {
    __nv_bfloat16 hx = __float2bfloat16(x), hy = __float2bfloat16(y);
    __nv_bfloat16 lx = __float2bfloat16(x - __bfloat162float(hx));
    __nv_bfloat16 ly = __float2bfloat16(y - __bfloat162float(hy));
    hi = ((uint32_t)__bfloat16_as_ushort(hy) << 16) | __bfloat16_as_ushort(hx);
    lo = ((uint32_t)__bfloat16_as_ushort(ly) << 16) | __bfloat16_as_ushort(lx);
}

// ---------------- warp MMA primitives (compute_80-legal) ----------------
__device__ __forceinline__ void ldmx4(uint32_t a, uint32_t* r) {
    asm volatile("ldmatrix.sync.aligned.m8n8.x4.shared.b16 {%0,%1,%2,%3}, [%4];"
        : "=r"(r[0]), "=r"(r[1]), "=r"(r[2]), "=r"(r[3]) : "r"(a));
}
__device__ __forceinline__ void mma16816(float* c, const uint32_t* a, uint32_t b0, uint32_t b1) {
    asm volatile("mma.sync.aligned.m16n8k16.row.col.f32.bf16.bf16.f32 "
        "{%0,%1,%2,%3}, {%4,%5,%6,%7}, {%8,%9}, {%0,%1,%2,%3};"
        : "+f"(c[0]), "+f"(c[1]), "+f"(c[2]), "+f"(c[3])
        : "r"(a[0]), "r"(a[1]), "r"(a[2]), "r"(a[3]), "r"(b0), "r"(b1));
}
__device__ __forceinline__ uint32_t a_addr(uint32_t base, int lane, int r0, int k0) {
    int row = r0 + (lane & 15);
    int chunk = (k0 >> 3) + ((lane >> 4) & 1);
    return base + SWZ(row * 128 + chunk * 16);
}
__device__ __forceinline__ uint32_t b_addr(uint32_t base, int lane, int j0, int k0) {
    int row = j0 + (lane & 7) + ((lane & 16) ? 8 : 0);
    int chunk = (k0 >> 3) + ((lane >> 3) & 1);
    return base + SWZ(row * 128 + chunk * 16);
}

// ---------------------------------------------------------------
// K0: zero accumulators
// ---------------------------------------------------------------
__global__ void zero_kernel() {
    int idx = blockIdx.x * blockDim.x + threadIdx.x;
    if (idx < NN * OO) g_agg[idx] = 0.f;
    if (idx < OUT_DIM) { g_sums[idx] = 0.f; g_sumsq[idx] = 0.f; }
    if (idx < OO)      { g_s2[idx] = 0.f;   g_q2[idx] = 0.f; }
}

// ---------------------------------------------------------------
// K_pre: P_d[n][j] = b[j] + n_feat[n]·W[j,0:64]
//        P_s[n][j] =        n_feat[n]·W[j,64:128]
// ---------------------------------------------------------------
__global__ __launch_bounds__(256)
void pre_kernel(const float* __restrict__ n_feat,
                const float* __restrict__ W,
                const float* __restrict__ b) {
    __shared__ float4 sn[16];
    const int t = threadIdx.x;
    const int j = t & 127, tab = t >> 7;

    float wreg[64];
    const float* wrow = W + (size_t)j * IN_DIM + tab * 64;
#pragma unroll
    for (int q = 0; q < 16; q++) {
        float4 v = *(const float4*)(wrow + q * 4);
        wreg[q * 4 + 0] = v.x; wreg[q * 4 + 1] = v.y;
        wreg[q * 4 + 2] = v.z; wreg[q * 4 + 3] = v.w;
    }
    const float bj = (tab == 0) ? __ldg(b + j) : 0.f;
    float* outT = (tab == 0) ? g_Pd : g_Ps;

    for (int n = blockIdx.x; n < NN; n += gridDim.x) {
        __syncthreads();
        if (t < 16) sn[t] = *(const float4*)(n_feat + (size_t)n * 64 + t * 4);
        __syncthreads();
        float acc = bj;
#pragma unroll
        for (int q = 0; q < 16; q++) {
            float4 v = sn[q];
            acc = fmaf(v.x, wreg[q * 4 + 0], acc);
            acc = fmaf(v.y, wreg[q * 4 + 1], acc);
            acc = fmaf(v.z, wreg[q * 4 + 2], acc);
            acc = fmaf(v.w, wreg[q * 4 + 3], acc);
        }
        outT[(size_t)n * 128 + j] = acc;
    }
}

// ---------------------------------------------------------------
// smem tile loaders (bf16 hi/lo split, SW128-swizzled, 128B rows)
// ---------------------------------------------------------------
__device__ __forceinline__ void load_w_tiles(char* smem, const float* __restrict__ W, int tid) {
    for (int idx = tid; idx < 4096; idx += 512) {
        int j = idx >> 5, cp = idx & 31;
        float2 v = *(const float2*)(W + (size_t)j * IN_DIM + 128 + cp * 2);
        uint32_t hi, lo; split2(v.x, v.y, hi, lo);
        uint32_t off = SWZ(j * 128 + cp * 4);
        *(uint32_t*)(smem + SM_BHI + off) = hi;
        *(uint32_t*)(smem + SM_BLO + off) = lo;
    }
}
__device__ __forceinline__ void load_e_tile(char* smem, const float* __restrict__ e_feat,
                                            int e0, int tid) {
    for (int idx = tid; idx < 4096; idx += 512) {
        int r = idx >> 5, cp = idx & 31;
        float2 v = *(const float2*)(e_feat + (size_t)(e0 + r) * 64 + cp * 2);
        uint32_t hi, lo; split2(v.x, v.y, hi, lo);
        uint32_t off = SWZ(r * 128 + cp * 4);
        *(uint32_t*)(smem + SM_AHI + off) = hi;
        *(uint32_t*)(smem + SM_ALO + off) = lo;
    }
}

// tile GEMM core: 8 ntile accumulators (4 "filt-half", 4 "core-half")
__device__ __forceinline__ void tile_mma(uint32_t sb, int lane, int m0, int cg, float* acc) {
#pragma unroll
    for (int k0 = 0; k0 < 64; k0 += 16) {
        uint32_t ah[4], al[4];
        ldmx4(a_addr(sb + SM_AHI, lane, m0, k0), ah);
        ldmx4(a_addr(sb + SM_ALO, lane, m0, k0), al);
#pragma unroll
        for (int half = 0; half < 2; half++) {
#pragma unroll
            for (int np = 0; np < 2; np++) {
                int j0 = half * 64 + cg * 32 + np * 16;
                uint32_t bh[4], bl[4];
                ldmx4(b_addr(sb + SM_BHI, lane, j0, k0), bh);
                ldmx4(b_addr(sb + SM_BLO, lane, j0, k0), bl);
                float* c0 = acc + (half * 4 + np * 2) * 4;
                float* c1 = c0 + 4;
                mma16816(c0, ah, bh[0], bh[1]);
                mma16816(c1, ah, bh[2], bh[3]);
                mma16816(c0, al, bh[0], bh[1]);
                mma16816(c1, al, bh[2], bh[3]);
                mma16816(c0, ah, bl[0], bl[1]);
                mma16816(c1, ah, bl[2], bl[3]);
            }
        }
    }
}

// ---------------------------------------------------------------
// pass1: per-edge h = MMA + Pd[dst] + Ps[src]; store h + BN1 stats
// ---------------------------------------------------------------
__global__ __launch_bounds__(512, 1)
void pass1_kernel(const float* __restrict__ e_feat,
                  const int* __restrict__ src, const int* __restrict__ dst,
                  const float* __restrict__ W) {
    extern __shared__ char smem[];
    const uint32_t sb = s2u(smem);
    const int tid = threadIdx.x, wid = tid >> 5, lane = tid & 31;
    const int m0 = (wid & 7) * 16, cg = wid >> 3;
    const int g = lane >> 2, t = lane & 3;

    load_w_tiles(smem, W, tid);
    __syncthreads();

    float cs[16], cq[16];
#pragma unroll
    for (int k = 0; k < 16; k++) { cs[k] = 0.f; cq[k] = 0.f; }

    for (int tile = blockIdx.x; tile < NTILES; tile += gridDim.x) {
        const int e0 = tile * 128;
        __syncthreads();
        load_e_tile(smem, e_feat, e0, tid);
        __syncthreads();

        float acc[32];
#pragma unroll
        for (int k = 0; k < 32; k++) acc[k] = 0.f;
        tile_mma(sb, lane, m0, cg, acc);

        const int e1 = e0 + m0 + g, e2 = e1 + 8;
        const int d1 = __ldg(dst + e1), s1 = __ldg(src + e1);
        const int d2 = __ldg(dst + e2), s2 = __ldg(src + e2);
        const float* Pd1 = g_Pd + (size_t)d1 * 128;
        const float* Ps1 = g_Ps + (size_t)s1 * 128;
        const float* Pd2 = g_Pd + (size_t)d2 * 128;
        const float* Ps2 = g_Ps + (size_t)s2 * 128;
        float* h1 = g_h + (size_t)e1 * OUT_DIM;
        float* h2 = g_h + (size_t)e2 * OUT_DIM;
#pragma unroll
        for (int slot = 0; slot < 8; slot++) {
            int col = (slot >> 2) * 64 + cg * 32 + (slot & 3) * 8 + t * 2;
            float2 pa = __ldg((const float2*)(Pd1 + col));
            float2 pb = __ldg((const float2*)(Ps1 + col));
            float2 pc = __ldg((const float2*)(Pd2 + col));
            float2 pd = __ldg((const float2*)(Ps2 + col));
            float h0 = acc[slot * 4 + 0] + pa.x + pb.x;
            float h1v = acc[slot * 4 + 1] + pa.y + pb.y;
            float h2v = acc[slot * 4 + 2] + pc.x + pd.x;
            float h3 = acc[slot * 4 + 3] + pc.y + pd.y;
            *(float2*)(h1 + col) = make_float2(h0, h1v);
            *(float2*)(h2 + col) = make_float2(h2v, h3);
            cs[slot * 2 + 0] += h0 + h2v;
            cs[slot * 2 + 1] += h1v + h3;
            cq[slot * 2 + 0] += h0 * h0 + h2v * h2v;
            cq[slot * 2 + 1] += h1v * h1v + h3 * h3;
        }
    }

    // reduce over g (lanes differing in bits 2..4), then RED per column
#pragma unroll
    for (int k = 0; k < 16; k++) {
#pragma unroll
        for (int m = 4; m < 32; m <<= 1) {
            cs[k] += __shfl_xor_sync(0xffffffffu, cs[k], m);
            cq[k] += __shfl_xor_sync(0xffffffffu, cq[k], m);
        }
    }
    if (lane < 4) {
#pragma unroll
        for (int slot = 0; slot < 8; slot++) {
            int col = (slot >> 2) * 64 + cg * 32 + (slot & 3) * 8 + lane * 2;
            asm volatile("red.global.add.v2.f32 [%0], {%1,%2};"
                :: "l"(g_sums + col), "f"(cs[slot * 2]), "f"(cs[slot * 2 + 1]) : "memory");
            asm volatile("red.global.add.v2.f32 [%0], {%1,%2};"
                :: "l"(g_sumsq + col), "f"(cq[slot * 2]), "f"(cq[slot * 2 + 1]) : "memory");
        }
    }
}

// ---------------------------------------------------------------
// finalize1: BN1 scale/shift
// ---------------------------------------------------------------
__global__ void finalize1_kernel(const float* __restrict__ g1,
                                 const float* __restrict__ beta1) {
    int c = threadIdx.x;
    if (c >= OUT_DIM) return;
    float mean = g_sums[c] / (float)EE;
    float var  = g_sumsq[c] / (float)EE - mean * mean;
    float sc = rsqrtf(var + EPS) * g1[c];
    g_scale1[c] = sc;
    g_shift1[c] = beta1[c] - mean * sc;
}

// ---------------------------------------------------------------
// act_scatter: BN1 apply + sigmoid*softplus gate + red.v4 scatter
//   (R3-proven kernel: 108us, DRAM-bound on g_h read)
// ---------------------------------------------------------------
__global__ __launch_bounds__(256)
void act_scatter_kernel(const int* __restrict__ dst) {
    int idx = blockIdx.x * blockDim.x + threadIdx.x;   // over EE*16
    int e  = idx >> 4;
    int cg = (idx & 15) * 4;
    const float* hp = g_h + (size_t)e * OUT_DIM;
    float4 f4 = *(const float4*)(hp + cg);
    float4 g4 = *(const float4*)(hp + cg + 64);
    float4 s1 = *(const float4*)(g_scale1 + cg);
    float4 h1 = *(const float4*)(g_shift1 + cg);
    float4 s2 = *(const float4*)(g_scale1 + cg + 64);
    float4 h2 = *(const float4*)(g_shift1 + cg + 64);

    float m0, m1, m2, m3;
    {
        float f = f4.x * s1.x + h1.x, g = g4.x * s2.x + h2.x;
        m0 = (1.f / (1.f + expf(-f))) * softplus_f(g);
        f = f4.y * s1.y + h1.y; g = g4.y * s2.y + h2.y;
        m1 = (1.f / (1.f + expf(-f))) * softplus_f(g);
        f = f4.z * s1.z + h1.z; g = g4.z * s2.z + h2.z;
        m2 = (1.f / (1.f + expf(-f))) * softplus_f(g);
        f = f4.w * s1.w + h1.w; g = g4.w * s2.w + h2.w;
        m3 = (1.f / (1.f + expf(-f))) * softplus_f(g);
    }
    float* ap = g_agg + (size_t)__ldg(dst + e) * 64 + cg;
    asm volatile("red.global.add.v4.f32 [%0], {%1,%2,%3,%4};"
                 :: "l"(ap), "f"(m0), "f"(m1), "f"(m2), "f"(m3) : "memory");
}

// ---------------------------------------------------------------
// BN2 stats + finalize + output
// ---------------------------------------------------------------
__global__ void agg_stats_kernel() {
    __shared__ float sh[4][64], shq[4][64];
    int c  = threadIdx.x & 63;
    int rg = threadIdx.x >> 6;
    int r0 = blockIdx.x * 250;
    float s = 0.f, q = 0.f;
    for (int r = r0 + rg; r < r0 + 250; r += 4) {
        float v = g_agg[r * 64 + c];
        s += v;
        q = fmaf(v, v, q);
    }
    sh[rg][c] = s; shq[rg][c] = q;
    __syncthreads();
    if (threadIdx.x < 64) {
        atomicAdd(&g_s2[c], sh[0][c] + sh[1][c] + sh[2][c] + sh[3][c]);
        atomicAdd(&g_q2[c], shq[0][c] + shq[1][c] + shq[2][c] + shq[3][c]);
    }
}

__global__ void finalize2_kernel(const float* __restrict__ g2,
                                 const float* __restrict__ beta2) {
    int c = threadIdx.x;
    if (c >= OO) return;
    float mean = g_s2[c] / (float)NN;
    float var  = g_q2[c] / (float)NN - mean * mean;
    float sc = rsqrtf(var + EPS) * g2[c];
    g_scale2[c] = sc;
    g_shift2[c] = beta2[c] - mean * sc;
}

__global__ void output_kernel(const float* __restrict__ n_feat,
                              float* __restrict__ out) {
    int idx = blockIdx.x * blockDim.x + threadIdx.x;
    if (idx >= NN * OO) return;
    int c = idx & 63;
    float v = g_agg[idx] * g_scale2[c] + g_shift2[c] + n_feat[idx];
    out[idx] = softplus_f(v);
}

// ---------------------------------------------------------------
extern "C" void kernel_launch(void* const* d_in, const int* in_sizes, int n_in,
                              void* d_out, int out_size) {
    const float* n_feat = (const float*)d_in[0];
    const float* e_feat = (const float*)d_in[1];
    const int*   src    = (const int*)  d_in[2];
    const int*   dst    = (const int*)  d_in[3];
    const float* W      = (const float*)d_in[4];
    const float* b      = (const float*)d_in[5];
    const float* g1     = (const float*)d_in[6];
    const float* beta1  = (const float*)d_in[7];
    const float* g2     = (const float*)d_in[8];
    const float* beta2  = (const float*)d_in[9];
    float* out = (float*)d_out;

    cudaFuncSetAttribute(pass1_kernel, cudaFuncAttributeMaxDynamicSharedMemorySize, SM_TOTAL);

    zero_kernel<<<(NN * OO + 255) / 256, 256>>>();
    pre_kernel<<<444, 256>>>(n_feat, W, b);
    pass1_kernel<<<148, 512, SM_TOTAL>>>(e_feat, src, dst, W);
    finalize1_kernel<<<1, 128>>>(g1, beta1);
    act_scatter_kernel<<<(EE * 16) / 256, 256>>>(dst);
    agg_stats_kernel<<<200, 256>>>();
    finalize2_kernel<<<1, 64>>>(g2, beta2);
    output_kernel<<<(NN * OO + 255) / 256, 256>>>(n_feat, out);
}

// round 12
// speedup vs baseline: 2.2335x; 1.1836x over previous
#include <cuda_runtime.h>
#include <cuda_bf16.h>
#include <cuda_fp16.h>
#include <math.h>
#include <stdint.h>

#define NN 50000
#define EE 800000
#define OO 64
#define IN_DIM 192
#define OUT_DIM 128
#define EPS 1e-5f
#define NTILES (EE / 128)
#define GRID 148

// ---- static device scratch (no runtime allocation) ----
__device__ __half g_h[(size_t)EE * OUT_DIM];  // 204.8 MB fp16 edge GEMM output
__device__ float g_Pd[(size_t)NN * 128];      // n_feat @ W_d^T + b   (25.6 MB)
__device__ float g_Ps[(size_t)NN * 128];      // n_feat @ W_s^T       (25.6 MB)
__device__ float g_agg[NN * OO];
__device__ float g_sums[OUT_DIM], g_sumsq[OUT_DIM];
__device__ float g_scale1[OUT_DIM], g_shift1[OUT_DIM];
__device__ float g_s2[OO], g_q2[OO], g_scale2[OO], g_shift2[OO];

__device__ __forceinline__ float softplus_f(float x) {
    return fmaxf(x, 0.f) + log1pf(expf(-fabsf(x)));
}

__device__ __forceinline__ uint32_t s2u(const void* p) {
    uint32_t a;
    asm("{ .reg .u64 t; cvta.to.shared.u64 t, %1; cvt.u32.u64 %0, t; }" : "=r"(a) : "l"(p));
    return a;
}

#define SWZ(o) ((o) ^ ((((uint32_t)(o)) >> 3) & 0x70))

// dynamic smem layout (bytes)
#define SM_AHI   0
#define SM_ALO   16384
#define SM_BHI   32768
#define SM_BLO   49152
#define SM_ST0   65536
#define SM_ST1   98304
#define SM_TOTAL 131072

// pack two floats -> bf16x2 hi word + lo (residual) word
__device__ __forceinline__ void split2(float x, float y, uint32_t& hi, uint32_t& lo) {
    __nv_bfloat16 hx = __float2bfloat16(x), hy = __float2bfloat16(y);
    __nv_bfloat16 lx = __float2bfloat16(x - __bfloat162float(hx));
    __nv_bfloat16 ly = __float2bfloat16(y - __bfloat162float(hy));
    hi = ((uint32_t)__bfloat16_as_ushort(hy) << 16) | __bfloat16_as_ushort(hx);
    lo = ((uint32_t)__bfloat16_as_ushort(ly) << 16) | __bfloat16_as_ushort(lx);
}

// ---------------- warp MMA primitives (compute_80-legal) ----------------
__device__ __forceinline__ void ldmx4(uint32_t a, uint32_t* r) {
    asm volatile("ldmatrix.sync.aligned.m8n8.x4.shared.b16 {%0,%1,%2,%3}, [%4];"
        : "=r"(r[0]), "=r"(r[1]), "=r"(r[2]), "=r"(r[3]) : "r"(a));
}
__device__ __forceinline__ void mma16816(float* c, const uint32_t* a, uint32_t b0, uint32_t b1) {
    asm volatile("mma.sync.aligned.m16n8k16.row.col.f32.bf16.bf16.f32 "
        "{%0,%1,%2,%3}, {%4,%5,%6,%7}, {%8,%9}, {%0,%1,%2,%3};"
        : "+f"(c[0]), "+f"(c[1]), "+f"(c[2]), "+f"(c[3])
        : "r"(a[0]), "r"(a[1]), "r"(a[2]), "r"(a[3]), "r"(b0), "r"(b1));
}
__device__ __forceinline__ uint32_t a_addr(uint32_t base, int lane, int r0, int k0) {
    int row = r0 + (lane & 15);
    int chunk = (k0 >> 3) + ((lane >> 4) & 1);
    return base + SWZ(row * 128 + chunk * 16);
}
__device__ __forceinline__ uint32_t b_addr(uint32_t base, int lane, int j0, int k0) {
    int row = j0 + (lane & 7) + ((lane & 16) ? 8 : 0);
    int chunk = (k0 >> 3) + ((lane >> 3) & 1);
    return base + SWZ(row * 128 + chunk * 16);
}

// ---------------------------------------------------------------
// K0: zero accumulators
// ---------------------------------------------------------------
__global__ void zero_kernel() {
    int idx = blockIdx.x * blockDim.x + threadIdx.x;
    if (idx < NN * OO) g_agg[idx] = 0.f;
    if (idx < OUT_DIM) { g_sums[idx] = 0.f; g_sumsq[idx] = 0.f; }
    if (idx < OO)      { g_s2[idx] = 0.f;   g_q2[idx] = 0.f; }
}

// ---------------------------------------------------------------
// K_pre: P_d[n][j] = b[j] + n_feat[n]·W[j,0:64]
//        P_s[n][j] =        n_feat[n]·W[j,64:128]
//   4 node-rows per barrier iteration (latency amortized 4x)
// ---------------------------------------------------------------
__global__ __launch_bounds__(256)
void pre_kernel(const float* __restrict__ n_feat,
                const float* __restrict__ W,
                const float* __restrict__ b) {
    __shared__ float4 sn[4][16];
    const int t = threadIdx.x;
    const int j = t & 127, tab = t >> 7;

    float wreg[64];
    const float* wrow = W + (size_t)j * IN_DIM + tab * 64;
#pragma unroll
    for (int q = 0; q < 16; q++) {
        float4 v = *(const float4*)(wrow + q * 4);
        wreg[q * 4 + 0] = v.x; wreg[q * 4 + 1] = v.y;
        wreg[q * 4 + 2] = v.z; wreg[q * 4 + 3] = v.w;
    }
    const float bj = (tab == 0) ? __ldg(b + j) : 0.f;
    float* outT = (tab == 0) ? g_Pd : g_Ps;

    for (int n0 = blockIdx.x * 4; n0 < NN; n0 += gridDim.x * 4) {
        __syncthreads();
        if (t < 64)
            sn[t >> 4][t & 15] = *(const float4*)(n_feat + (size_t)(n0 + (t >> 4)) * 64 + (t & 15) * 4);
        __syncthreads();
        float a0 = bj, a1 = bj, a2 = bj, a3 = bj;
#pragma unroll
        for (int q = 0; q < 16; q++) {
            float4 v0 = sn[0][q], v1 = sn[1][q], v2 = sn[2][q], v3 = sn[3][q];
            a0 = fmaf(v0.x, wreg[q*4+0], a0); a0 = fmaf(v0.y, wreg[q*4+1], a0);
            a0 = fmaf(v0.z, wreg[q*4+2], a0); a0 = fmaf(v0.w, wreg[q*4+3], a0);
            a1 = fmaf(v1.x, wreg[q*4+0], a1); a1 = fmaf(v1.y, wreg[q*4+1], a1);
            a1 = fmaf(v1.z, wreg[q*4+2], a1); a1 = fmaf(v1.w, wreg[q*4+3], a1);
            a2 = fmaf(v2.x, wreg[q*4+0], a2); a2 = fmaf(v2.y, wreg[q*4+1], a2);
            a2 = fmaf(v2.z, wreg[q*4+2], a2); a2 = fmaf(v2.w, wreg[q*4+3], a2);
            a3 = fmaf(v3.x, wreg[q*4+0], a3); a3 = fmaf(v3.y, wreg[q*4+1], a3);
            a3 = fmaf(v3.z, wreg[q*4+2], a3); a3 = fmaf(v3.w, wreg[q*4+3], a3);
        }
        outT[(size_t)(n0 + 0) * 128 + j] = a0;
        outT[(size_t)(n0 + 1) * 128 + j] = a1;
        outT[(size_t)(n0 + 2) * 128 + j] = a2;
        outT[(size_t)(n0 + 3) * 128 + j] = a3;
    }
}

// ---------------------------------------------------------------
// pass1 helpers
// ---------------------------------------------------------------
__device__ __forceinline__ void load_w_tiles(char* smem, const float* __restrict__ W, int tid) {
    for (int idx = tid; idx < 4096; idx += 512) {
        int j = idx >> 5, cp = idx & 31;
        float2 v = *(const float2*)(W + (size_t)j * IN_DIM + 128 + cp * 2);
        uint32_t hi, lo; split2(v.x, v.y, hi, lo);
        uint32_t off = SWZ(j * 128 + cp * 4);
        *(uint32_t*)(smem + SM_BHI + off) = hi;
        *(uint32_t*)(smem + SM_BLO + off) = lo;
    }
}

// cp.async next e-tile (raw fp32, 32KB) into staging buffer
__device__ __forceinline__ void cp_tile(uint32_t sdst, const float* __restrict__ gsrc, int tid) {
#pragma unroll
    for (int k = 0; k < 4; k++) {
        int c = tid + k * 512;                       // 16B chunk index (0..2047)
        asm volatile("cp.async.cg.shared.global [%0], [%1], 16;"
                     :: "r"(sdst + c * 16), "l"(gsrc + c * 4) : "memory");
    }
}
#define CP_COMMIT() asm volatile("cp.async.commit_group;" ::: "memory")
#define CP_WAIT1()  asm volatile("cp.async.wait_group 1;" ::: "memory")

// convert staged fp32 tile -> bf16 hi/lo swizzled operand smem
__device__ __forceinline__ void convert_tile(char* smem, int stoff, int tid) {
    const float4* st = (const float4*)(smem + stoff);
#pragma unroll
    for (int k = 0; k < 4; k++) {
        int c = tid + k * 512;
        float4 v = st[c];
        int row = c >> 4;
        int c0  = (c & 15) * 4;
        uint32_t h0, l0, h1, l1;
        split2(v.x, v.y, h0, l0);
        split2(v.z, v.w, h1, l1);
        uint32_t o = SWZ(row * 128 + c0 * 2);
        *(uint2*)(smem + SM_AHI + o) = make_uint2(h0, h1);
        *(uint2*)(smem + SM_ALO + o) = make_uint2(l0, l1);
    }
}

// tile GEMM core: 8 ntile accumulators (4 "filt-half", 4 "core-half")
__device__ __forceinline__ void tile_mma(uint32_t sb, int lane, int m0, int cg, float* acc) {
#pragma unroll
    for (int k0 = 0; k0 < 64; k0 += 16) {
        uint32_t ah[4], al[4];
        ldmx4(a_addr(sb + SM_AHI, lane, m0, k0), ah);
        ldmx4(a_addr(sb + SM_ALO, lane, m0, k0), al);
#pragma unroll
        for (int half = 0; half < 2; half++) {
#pragma unroll
            for (int np = 0; np < 2; np++) {
                int j0 = half * 64 + cg * 32 + np * 16;
                uint32_t bh[4], bl[4];
                ldmx4(b_addr(sb + SM_BHI, lane, j0, k0), bh);
                ldmx4(b_addr(sb + SM_BLO, lane, j0, k0), bl);
                float* c0 = acc + (half * 4 + np * 2) * 4;
                float* c1 = c0 + 4;
                mma16816(c0, ah, bh[0], bh[1]);
                mma16816(c1, ah, bh[2], bh[3]);
                mma16816(c0, al, bh[0], bh[1]);
                mma16816(c1, al, bh[2], bh[3]);
                mma16816(c0, ah, bl[0], bl[1]);
                mma16816(c1, ah, bl[2], bl[3]);
            }
        }
    }
}

// ---------------------------------------------------------------
// pass1: per-edge h = MMA + Pd[dst] + Ps[src]; store h(fp16) + BN1 stats
//   cp.async double-buffered e-tile pipeline
// ---------------------------------------------------------------
__global__ __launch_bounds__(512, 1)
void pass1_kernel(const float* __restrict__ e_feat,
                  const int* __restrict__ src, const int* __restrict__ dst,
                  const float* __restrict__ W) {
    extern __shared__ char smem[];
    const uint32_t sb = s2u(smem);
    const int tid = threadIdx.x, wid = tid >> 5, lane = tid & 31;
    const int m0 = (wid & 7) * 16, cg = wid >> 3;
    const int g = lane >> 2, t = lane & 3;

    load_w_tiles(smem, W, tid);

    float cs[16], cq[16];
#pragma unroll
    for (int k = 0; k < 16; k++) { cs[k] = 0.f; cq[k] = 0.f; }

    // pipeline prologue: prefetch tiles blockIdx.x and blockIdx.x+GRID
    int tile = blockIdx.x;
    if (tile < NTILES) cp_tile(sb + SM_ST0, e_feat + (size_t)tile * 8192, tid);
    CP_COMMIT();
    if (tile + GRID < NTILES) cp_tile(sb + SM_ST1, e_feat + (size_t)(tile + GRID) * 8192, tid);
    CP_COMMIT();

    int buf = 0;
    for (; tile < NTILES; tile += GRID, buf ^= 1) {
        CP_WAIT1();
        __syncthreads();                               // stage[buf] ready; prev MMA readers done
        convert_tile(smem, buf ? SM_ST1 : SM_ST0, tid);
        __syncthreads();                               // operands ready; stage[buf] reads done
        int nxt = tile + 2 * GRID;
        if (nxt < NTILES) cp_tile(sb + (buf ? SM_ST1 : SM_ST0), e_feat + (size_t)nxt * 8192, tid);
        CP_COMMIT();

        float acc[32];
#pragma unroll
        for (int k = 0; k < 32; k++) acc[k] = 0.f;
        tile_mma(sb, lane, m0, cg, acc);

        const int e0 = tile * 128;
        const int e1 = e0 + m0 + g, e2 = e1 + 8;
        const int d1 = __ldg(dst + e1), s1 = __ldg(src + e1);
        const int d2 = __ldg(dst + e2), s2 = __ldg(src + e2);
        const float* Pd1 = g_Pd + (size_t)d1 * 128;
        const float* Ps1 = g_Ps + (size_t)s1 * 128;
        const float* Pd2 = g_Pd + (size_t)d2 * 128;
        const float* Ps2 = g_Ps + (size_t)s2 * 128;
        __half* h1 = g_h + (size_t)e1 * OUT_DIM;
        __half* h2 = g_h + (size_t)e2 * OUT_DIM;
#pragma unroll
        for (int slot = 0; slot < 8; slot++) {
            int col = (slot >> 2) * 64 + cg * 32 + (slot & 3) * 8 + t * 2;
            float2 pa = __ldg((const float2*)(Pd1 + col));
            float2 pb = __ldg((const float2*)(Ps1 + col));
            float2 pc = __ldg((const float2*)(Pd2 + col));
            float2 pd = __ldg((const float2*)(Ps2 + col));
            float h0  = acc[slot * 4 + 0] + pa.x + pb.x;
            float h1v = acc[slot * 4 + 1] + pa.y + pb.y;
            float h2v = acc[slot * 4 + 2] + pc.x + pd.x;
            float h3  = acc[slot * 4 + 3] + pc.y + pd.y;
            *(__half2*)(h1 + col) = __floats2half2_rn(h0, h1v);
            *(__half2*)(h2 + col) = __floats2half2_rn(h2v, h3);
            cs[slot * 2 + 0] += h0 + h2v;
            cs[slot * 2 + 1] += h1v + h3;
            cq[slot * 2 + 0] += h0 * h0 + h2v * h2v;
            cq[slot * 2 + 1] += h1v * h1v + h3 * h3;
        }
    }

    // reduce over g (lanes differing in bits 2..4), then RED per column
#pragma unroll
    for (int k = 0; k < 16; k++) {
#pragma unroll
        for (int m = 4; m < 32; m <<= 1) {
            cs[k] += __shfl_xor_sync(0xffffffffu, cs[k], m);
            cq[k] += __shfl_xor_sync(0xffffffffu, cq[k], m);
        }
    }
    if (lane < 4) {
#pragma unroll
        for (int slot = 0; slot < 8; slot++) {
            int col = (slot >> 2) * 64 + cg * 32 + (slot & 3) * 8 + lane * 2;
            asm volatile("red.global.add.v2.f32 [%0], {%1,%2};"
                :: "l"(g_sums + col), "f"(cs[slot * 2]), "f"(cs[slot * 2 + 1]) : "memory");
            asm volatile("red.global.add.v2.f32 [%0], {%1,%2};"
                :: "l"(g_sumsq + col), "f"(cq[slot * 2]), "f"(cq[slot * 2 + 1]) : "memory");
        }
    }
}

// ---------------------------------------------------------------
// finalize1: BN1 scale/shift
// ---------------------------------------------------------------
__global__ void finalize1_kernel(const float* __restrict__ g1,
                                 const float* __restrict__ beta1) {
    int c = threadIdx.x;
    if (c >= OUT_DIM) return;
    float mean = g_sums[c] / (float)EE;
    float var  = g_sumsq[c] / (float)EE - mean * mean;
    float sc = rsqrtf(var + EPS) * g1[c];
    g_scale1[c] = sc;
    g_shift1[c] = beta1[c] - mean * sc;
}

// ---------------------------------------------------------------
// act_scatter: BN1 apply + sigmoid*softplus gate + red.v4 scatter
//   reads fp16 h (half the DRAM traffic of R3's version)
// ---------------------------------------------------------------
__global__ __launch_bounds__(256)
void act_scatter_kernel(const int* __restrict__ dst) {
    int idx = blockIdx.x * blockDim.x + threadIdx.x;   // over EE*16
    int e  = idx >> 4;
    int cg = (idx & 15) * 4;
    const __half2* hp = (const __half2*)(g_h + (size_t)e * OUT_DIM);
    float2 f01 = __half22float2(hp[(cg >> 1) + 0]);
    float2 f23 = __half22float2(hp[(cg >> 1) + 1]);
    float2 g01 = __half22float2(hp[(cg >> 1) + 32]);
    float2 g23 = __half22float2(hp[(cg >> 1) + 33]);
    float4 s1 = *(const float4*)(g_scale1 + cg);
    float4 h1 = *(const float4*)(g_shift1 + cg);
    float4 s2 = *(const float4*)(g_scale1 + cg + 64);
    float4 h2 = *(const float4*)(g_shift1 + cg + 64);

    float m0, m1, m2, m3;
    {
        float f = f01.x * s1.x + h1.x, g = g01.x * s2.x + h2.x;
        m0 = (1.f / (1.f + expf(-f))) * softplus_f(g);
        f = f01.y * s1.y + h1.y; g = g01.y * s2.y + h2.y;
        m1 = (1.f / (1.f + expf(-f))) * softplus_f(g);
        f = f23.x * s1.z + h1.z; g = g23.x * s2.z + h2.z;
        m2 = (1.f / (1.f + expf(-f))) * softplus_f(g);
        f = f23.y * s1.w + h1.w; g = g23.y * s2.w + h2.w;
        m3 = (1.f / (1.f + expf(-f))) * softplus_f(g);
    }
    float* ap = g_agg + (size_t)__ldg(dst + e) * 64 + cg;
    asm volatile("red.global.add.v4.f32 [%0], {%1,%2,%3,%4};"
                 :: "l"(ap), "f"(m0), "f"(m1), "f"(m2), "f"(m3) : "memory");
}

// ---------------------------------------------------------------
// BN2 stats + finalize + output
// ---------------------------------------------------------------
__global__ void agg_stats_kernel() {
    __shared__ float sh[4][64], shq[4][64];
    int c  = threadIdx.x & 63;
    int rg = threadIdx.x >> 6;
    int r0 = blockIdx.x * 250;
    float s = 0.f, q = 0.f;
    for (int r = r0 + rg; r < r0 + 250; r += 4) {
        float v = g_agg[r * 64 + c];
        s += v;
        q = fmaf(v, v, q);
    }
    sh[rg][c] = s; shq[rg][c] = q;
    __syncthreads();
    if (threadIdx.x < 64) {
        atomicAdd(&g_s2[c], sh[0][c] + sh[1][c] + sh[2][c] + sh[3][c]);
        atomicAdd(&g_q2[c], shq[0][c] + shq[1][c] + shq[2][c] + shq[3][c]);
    }
}

__global__ void finalize2_kernel(const float* __restrict__ g2,
                                 const float* __restrict__ beta2) {
    int c = threadIdx.x;
    if (c >= OO) return;
    float mean = g_s2[c] / (float)NN;
    float var  = g_q2[c] / (float)NN - mean * mean;
    float sc = rsqrtf(var + EPS) * g2[c];
    g_scale2[c] = sc;
    g_shift2[c] = beta2[c] - mean * sc;
}

__global__ void output_kernel(const float* __restrict__ n_feat,
                              float* __restrict__ out) {
    int idx = blockIdx.x * blockDim.x + threadIdx.x;
    if (idx >= NN * OO) return;
    int c = idx & 63;
    float v = g_agg[idx] * g_scale2[c] + g_shift2[c] + n_feat[idx];
    out[idx] = softplus_f(v);
}

// ---------------------------------------------------------------
extern "C" void kernel_launch(void* const* d_in, const int* in_sizes, int n_in,
                              void* d_out, int out_size) {
    const float* n_feat = (const float*)d_in[0];
    const float* e_feat = (const float*)d_in[1];
    const int*   src    = (const int*)  d_in[2];
    const int*   dst    = (const int*)  d_in[3];
    const float* W      = (const float*)d_in[4];
    const float* b      = (const float*)d_in[5];
    const float* g1     = (const float*)d_in[6];
    const float* beta1  = (const float*)d_in[7];
    const float* g2     = (const float*)d_in[8];
    const float* beta2  = (const float*)d_in[9];
    float* out = (float*)d_out;

    cudaFuncSetAttribute(pass1_kernel, cudaFuncAttributeMaxDynamicSharedMemorySize, SM_TOTAL);

    zero_kernel<<<(NN * OO + 255) / 256, 256>>>();
    pre_kernel<<<444, 256>>>(n_feat, W, b);
    pass1_kernel<<<GRID, 512, SM_TOTAL>>>(e_feat, src, dst, W);
    finalize1_kernel<<<1, 128>>>(g1, beta1);
    act_scatter_kernel<<<(EE * 16) / 256, 256>>>(dst);
    agg_stats_kernel<<<200, 256>>>();
    finalize2_kernel<<<1, 64>>>(g2, beta2);
    output_kernel<<<(NN * OO + 255) / 256, 256>>>(n_feat, out);
}

// round 17
// speedup vs baseline: 2.7103x; 1.2135x over previous
#include <cuda_runtime.h>
#include <cuda_bf16.h>
#include <cuda_fp16.h>
#include <math.h>
#include <stdint.h>

#define NN 50000
#define EE 800000
#define OO 64
#define IN_DIM 192
#define OUT_DIM 128
#define EPS 1e-5f
#define NTILES (EE / 128)
#define GRID 148

// ---- static device scratch (no runtime allocation) ----
__device__ __half g_h[(size_t)EE * OUT_DIM];   // 204.8 MB fp16 edge GEMM output
__device__ __half g_Pd[(size_t)NN * 128];      // permuted fp16: b + n@W_d^T (12.8 MB)
__device__ __half g_Ps[(size_t)NN * 128];      // permuted fp16: n@W_s^T     (12.8 MB)
__device__ float g_agg[NN * OO];
__device__ float g_sums[OUT_DIM], g_sumsq[OUT_DIM];
__device__ float g_scale1[OUT_DIM], g_shift1[OUT_DIM];
__device__ float g_s2[OO], g_q2[OO], g_scale2[OO], g_shift2[OO];

__device__ __forceinline__ float softplus_f(float x) {
    return fmaxf(x, 0.f) + log1pf(expf(-fabsf(x)));
}

__device__ __forceinline__ uint32_t s2u(const void* p) {
    uint32_t a;
    asm("{ .reg .u64 t; cvta.to.shared.u64 t, %1; cvt.u32.u64 %0, t; }" : "=r"(a) : "l"(p));
    return a;
}

#define SWZ(o) ((o) ^ ((((uint32_t)(o)) >> 3) & 0x70))

// dynamic smem layout (bytes)
#define SM_AHI   0
#define SM_ALO   16384
#define SM_BHI   32768
#define SM_BLO   49152
#define SM_ST0   65536
#define SM_ST1   98304
#define SM_TOTAL 131072

// P-table within-row permutation:
//   logical col j = h*64 + cg*32 + q*8 + 2t + e  ->  h*64 + cg*32 + t*8 + q*2 + e
// so thread (cg,t) reads its 4 q-pairs for one h as ONE uint4 (dense 16B).
__device__ __host__ __forceinline__ int p_perm(int j) {
    int h = j >> 6, r = j & 63;
    int cg = r >> 5, r2 = r & 31;
    int q = r2 >> 3, r3 = r2 & 7;
    int t = r3 >> 1, e = r3 & 1;
    return h * 64 + cg * 32 + t * 8 + q * 2 + e;
}

// pack two floats -> bf16x2 hi word + lo (residual) word
__device__ __forceinline__ void split2(float x, float y, uint32_t& hi, uint32_t& lo) {
    __nv_bfloat16 hx = __float2bfloat16(x), hy = __float2bfloat16(y);
    __nv_bfloat16 lx = __float2bfloat16(x - __bfloat162float(hx));
    __nv_bfloat16 ly = __float2bfloat16(y - __bfloat162float(hy));
    hi = ((uint32_t)__bfloat16_as_ushort(hy) << 16) | __bfloat16_as_ushort(hx);
    lo = ((uint32_t)__bfloat16_as_ushort(ly) << 16) | __bfloat16_as_ushort(lx);
}

// ---------------- warp MMA primitives (compute_80-legal) ----------------
__device__ __forceinline__ void ldmx4(uint32_t a, uint32_t* r) {
    asm volatile("ldmatrix.sync.aligned.m8n8.x4.shared.b16 {%0,%1,%2,%3}, [%4];"
        : "=r"(r[0]), "=r"(r[1]), "=r"(r[2]), "=r"(r[3]) : "r"(a));
}
__device__ __forceinline__ void mma16816(float* c, const uint32_t* a, uint32_t b0, uint32_t b1) {
    asm volatile("mma.sync.aligned.m16n8k16.row.col.f32.bf16.bf16.f32 "
        "{%0,%1,%2,%3}, {%4,%5,%6,%7}, {%8,%9}, {%0,%1,%2,%3};"
        : "+f"(c[0]), "+f"(c[1]), "+f"(c[2]), "+f"(c[3])
        : "r"(a[0]), "r"(a[1]), "r"(a[2]), "r"(a[3]), "r"(b0), "r"(b1));
}
__device__ __forceinline__ uint32_t a_addr(uint32_t base, int lane, int r0, int k0) {
    int row = r0 + (lane & 15);
    int chunk = (k0 >> 3) + ((lane >> 4) & 1);
    return base + SWZ(row * 128 + chunk * 16);
}
__device__ __forceinline__ uint32_t b_addr(uint32_t base, int lane, int j0, int k0) {
    int row = j0 + (lane & 7) + ((lane & 16) ? 8 : 0);
    int chunk = (k0 >> 3) + ((lane >> 3) & 1);
    return base + SWZ(row * 128 + chunk * 16);
}

// ---------------------------------------------------------------
// K_pre: zero accumulators (folded), then
//        P_d[n][perm(j)] = fp16(b[j] + n_feat[n]·W[j,0:64])
//        P_s[n][perm(j)] = fp16(       n_feat[n]·W[j,64:128])
// ---------------------------------------------------------------
__global__ __launch_bounds__(256)
void pre_kernel(const float* __restrict__ n_feat,
                const float* __restrict__ W,
                const float* __restrict__ b) {
    // folded zeroing (disjoint arrays; consumed by later kernels)
    int gidx = blockIdx.x * blockDim.x + threadIdx.x;
    for (int i = gidx; i < NN * OO / 4; i += gridDim.x * blockDim.x)
        ((float4*)g_agg)[i] = make_float4(0.f, 0.f, 0.f, 0.f);
    if (gidx < OUT_DIM) { g_sums[gidx] = 0.f; g_sumsq[gidx] = 0.f; }
    if (gidx < OO)      { g_s2[gidx] = 0.f;   g_q2[gidx] = 0.f; }

    __shared__ float4 sn[4][16];
    const int t = threadIdx.x;
    const int j = t & 127, tab = t >> 7;
    const int pj = p_perm(j);

    float wreg[64];
    const float* wrow = W + (size_t)j * IN_DIM + tab * 64;
#pragma unroll
    for (int q = 0; q < 16; q++) {
        float4 v = *(const float4*)(wrow + q * 4);
        wreg[q * 4 + 0] = v.x; wreg[q * 4 + 1] = v.y;
        wreg[q * 4 + 2] = v.z; wreg[q * 4 + 3] = v.w;
    }
    const float bj = (tab == 0) ? __ldg(b + j) : 0.f;
    __half* outT = (tab == 0) ? g_Pd : g_Ps;

    for (int n0 = blockIdx.x * 4; n0 < NN; n0 += gridDim.x * 4) {
        __syncthreads();
        if (t < 64)
            sn[t >> 4][t & 15] = *(const float4*)(n_feat + (size_t)(n0 + (t >> 4)) * 64 + (t & 15) * 4);
        __syncthreads();
        float a0 = bj, a1 = bj, a2 = bj, a3 = bj;
#pragma unroll
        for (int q = 0; q < 16; q++) {
            float4 v0 = sn[0][q], v1 = sn[1][q], v2 = sn[2][q], v3 = sn[3][q];
            a0 = fmaf(v0.x, wreg[q*4+0], a0); a0 = fmaf(v0.y, wreg[q*4+1], a0);
            a0 = fmaf(v0.z, wreg[q*4+2], a0); a0 = fmaf(v0.w, wreg[q*4+3], a0);
            a1 = fmaf(v1.x, wreg[q*4+0], a1); a1 = fmaf(v1.y, wreg[q*4+1], a1);
            a1 = fmaf(v1.z, wreg[q*4+2], a1); a1 = fmaf(v1.w, wreg[q*4+3], a1);
            a2 = fmaf(v2.x, wreg[q*4+0], a2); a2 = fmaf(v2.y, wreg[q*4+1], a2);
            a2 = fmaf(v2.z, wreg[q*4+2], a2); a2 = fmaf(v2.w, wreg[q*4+3], a2);
            a3 = fmaf(v3.x, wreg[q*4+0], a3); a3 = fmaf(v3.y, wreg[q*4+1], a3);
            a3 = fmaf(v3.z, wreg[q*4+2], a3); a3 = fmaf(v3.w, wreg[q*4+3], a3);
        }
        outT[(size_t)(n0 + 0) * 128 + pj] = __float2half(a0);
        outT[(size_t)(n0 + 1) * 128 + pj] = __float2half(a1);
        outT[(size_t)(n0 + 2) * 128 + pj] = __float2half(a2);
        outT[(size_t)(n0 + 3) * 128 + pj] = __float2half(a3);
    }
}

// ---------------------------------------------------------------
// pass1 helpers
// ---------------------------------------------------------------
__device__ __forceinline__ void load_w_tiles(char* smem, const float* __restrict__ W, int tid) {
    for (int idx = tid; idx < 4096; idx += 512) {
        int j = idx >> 5, cp = idx & 31;
        float2 v = *(const float2*)(W + (size_t)j * IN_DIM + 128 + cp * 2);
        uint32_t hi, lo; split2(v.x, v.y, hi, lo);
        uint32_t off = SWZ(j * 128 + cp * 4);
        *(uint32_t*)(smem + SM_BHI + off) = hi;
        *(uint32_t*)(smem + SM_BLO + off) = lo;
    }
}

// cp.async next e-tile (raw fp32, 32KB) into staging buffer
__device__ __forceinline__ void cp_tile(uint32_t sdst, const float* __restrict__ gsrc, int tid) {
#pragma unroll
    for (int k = 0; k < 4; k++) {
        int c = tid + k * 512;
        asm volatile("cp.async.cg.shared.global [%0], [%1], 16;"
                     :: "r"(sdst + c * 16), "l"(gsrc + c * 4) : "memory");
    }
}
#define CP_COMMIT() asm volatile("cp.async.commit_group;" ::: "memory")
#define CP_WAIT1()  asm volatile("cp.async.wait_group 1;" ::: "memory")

// convert staged fp32 tile -> bf16 hi/lo swizzled operand smem
__device__ __forceinline__ void convert_tile(char* smem, int stoff, int tid) {
    const float4* st = (const float4*)(smem + stoff);
#pragma unroll
    for (int k = 0; k < 4; k++) {
        int c = tid + k * 512;
        float4 v = st[c];
        int row = c >> 4;
        int c0  = (c & 15) * 4;
        uint32_t h0, l0, h1, l1;
        split2(v.x, v.y, h0, l0);
        split2(v.z, v.w, h1, l1);
        uint32_t o = SWZ(row * 128 + c0 * 2);
        *(uint2*)(smem + SM_AHI + o) = make_uint2(h0, h1);
        *(uint2*)(smem + SM_ALO + o) = make_uint2(l0, l1);
    }
}

// tile GEMM core: 8 ntile accumulators (4 "filt-half", 4 "core-half")
__device__ __forceinline__ void tile_mma(uint32_t sb, int lane, int m0, int cg, float* acc) {
#pragma unroll
    for (int k0 = 0; k0 < 64; k0 += 16) {
        uint32_t ah[4], al[4];
        ldmx4(a_addr(sb + SM_AHI, lane, m0, k0), ah);
        ldmx4(a_addr(sb + SM_ALO, lane, m0, k0), al);
#pragma unroll
        for (int half = 0; half < 2; half++) {
#pragma unroll
            for (int np = 0; np < 2; np++) {
                int j0 = half * 64 + cg * 32 + np * 16;
                uint32_t bh[4], bl[4];
                ldmx4(b_addr(sb + SM_BHI, lane, j0, k0), bh);
                ldmx4(b_addr(sb + SM_BLO, lane, j0, k0), bl);
                float* c0 = acc + (half * 4 + np * 2) * 4;
                float* c1 = c0 + 4;
                mma16816(c0, ah, bh[0], bh[1]);
                mma16816(c1, ah, bh[2], bh[3]);
                mma16816(c0, al, bh[0], bh[1]);
                mma16816(c1, al, bh[2], bh[3]);
                mma16816(c0, ah, bl[0], bl[1]);
                mma16816(c1, ah, bl[2], bl[3]);
            }
        }
    }
}

// ---------------------------------------------------------------
// pass1: per-edge h = MMA + Pd[dst] + Ps[src]; store h(fp16) + BN1 stats
//   cp.async double-buffered e-tile pipeline; dense permuted fp16 P gathers
// ---------------------------------------------------------------
__global__ __launch_bounds__(512, 1)
void pass1_kernel(const float* __restrict__ e_feat,
                  const int* __restrict__ src, const int* __restrict__ dst,
                  const float* __restrict__ W) {
    extern __shared__ char smem[];
    const uint32_t sb = s2u(smem);
    const int tid = threadIdx.x, wid = tid >> 5, lane = tid & 31;
    const int m0 = (wid & 7) * 16, cg = wid >> 3;
    const int g = lane >> 2, t = lane & 3;

    load_w_tiles(smem, W, tid);

    float cs[16], cq[16];
#pragma unroll
    for (int k = 0; k < 16; k++) { cs[k] = 0.f; cq[k] = 0.f; }

    int tile = blockIdx.x;
    if (tile < NTILES) cp_tile(sb + SM_ST0, e_feat + (size_t)tile * 8192, tid);
    CP_COMMIT();
    if (tile + GRID < NTILES) cp_tile(sb + SM_ST1, e_feat + (size_t)(tile + GRID) * 8192, tid);
    CP_COMMIT();

    int buf = 0;
    for (; tile < NTILES; tile += GRID, buf ^= 1) {
        // prefetch edge indices early (overlap with convert+MMA)
        const int e0 = tile * 128;
        const int e1 = e0 + m0 + g, e2 = e1 + 8;
        const int d1 = __ldg(dst + e1), s1 = __ldg(src + e1);
        const int d2 = __ldg(dst + e2), s2 = __ldg(src + e2);

        CP_WAIT1();
        __syncthreads();                               // stage[buf] ready; prev MMA readers done
        convert_tile(smem, buf ? SM_ST1 : SM_ST0, tid);
        __syncthreads();                               // operands ready; stage[buf] reads done
        int nxt = tile + 2 * GRID;
        if (nxt < NTILES) cp_tile(sb + (buf ? SM_ST1 : SM_ST0), e_feat + (size_t)nxt * 8192, tid);
        CP_COMMIT();

        float acc[32];
#pragma unroll
        for (int k = 0; k < 32; k++) acc[k] = 0.f;
        tile_mma(sb, lane, m0, cg, acc);

        const uint4* Pd1 = (const uint4*)(g_Pd + (size_t)d1 * 128);
        const uint4* Ps1 = (const uint4*)(g_Ps + (size_t)s1 * 128);
        const uint4* Pd2 = (const uint4*)(g_Pd + (size_t)d2 * 128);
        const uint4* Ps2 = (const uint4*)(g_Ps + (size_t)s2 * 128);
        __half* h1p = g_h + (size_t)e1 * OUT_DIM;
        __half* h2p = g_h + (size_t)e2 * OUT_DIM;
#pragma unroll
        for (int h = 0; h < 2; h++) {
            const int u4 = h * 8 + cg * 4 + t;        // dense 16B: 4 q-pairs for (h,cg,t)
            uint4 va = __ldg(Pd1 + u4);
            uint4 vb = __ldg(Ps1 + u4);
            uint4 vc = __ldg(Pd2 + u4);
            uint4 vd = __ldg(Ps2 + u4);
            const uint32_t* wa = (const uint32_t*)&va;
            const uint32_t* wb = (const uint32_t*)&vb;
            const uint32_t* wc = (const uint32_t*)&vc;
            const uint32_t* wd = (const uint32_t*)&vd;
#pragma unroll
            for (int q = 0; q < 4; q++) {
                float2 fa = __half22float2(*(const __half2*)&wa[q]);
                float2 fb = __half22float2(*(const __half2*)&wb[q]);
                float2 fc = __half22float2(*(const __half2*)&wc[q]);
                float2 fd = __half22float2(*(const __half2*)&wd[q]);
                const int s = h * 4 + q;
                const int col = h * 64 + cg * 32 + q * 8 + t * 2;
                float h0  = acc[s * 4 + 0] + fa.x + fb.x;
                float h1v = acc[s * 4 + 1] + fa.y + fb.y;
                float h2v = acc[s * 4 + 2] + fc.x + fd.x;
                float h3  = acc[s * 4 + 3] + fc.y + fd.y;
                *(__half2*)(h1p + col) = __floats2half2_rn(h0, h1v);
                *(__half2*)(h2p + col) = __floats2half2_rn(h2v, h3);
                cs[s * 2 + 0] += h0 + h2v;
                cs[s * 2 + 1] += h1v + h3;
                cq[s * 2 + 0] += h0 * h0 + h2v * h2v;
                cq[s * 2 + 1] += h1v * h1v + h3 * h3;
            }
        }
    }

    // reduce over g (lanes differing in bits 2..4), then RED per column
#pragma unroll
    for (int k = 0; k < 16; k++) {
#pragma unroll
        for (int m = 4; m < 32; m <<= 1) {
            cs[k] += __shfl_xor_sync(0xffffffffu, cs[k], m);
            cq[k] += __shfl_xor_sync(0xffffffffu, cq[k], m);
        }
    }
    if (lane < 4) {
#pragma unroll
        for (int slot = 0; slot < 8; slot++) {
            int col = (slot >> 2) * 64 + cg * 32 + (slot & 3) * 8 + lane * 2;
            asm volatile("red.global.add.v2.f32 [%0], {%1,%2};"
                :: "l"(g_sums + col), "f"(cs[slot * 2]), "f"(cs[slot * 2 + 1]) : "memory");
            asm volatile("red.global.add.v2.f32 [%0], {%1,%2};"
                :: "l"(g_sumsq + col), "f"(cq[slot * 2]), "f"(cq[slot * 2 + 1]) : "memory");
        }
    }
}

// ---------------------------------------------------------------
// finalize1: BN1 scale/shift
// ---------------------------------------------------------------
__global__ void finalize1_kernel(const float* __restrict__ g1,
                                 const float* __restrict__ beta1) {
    int c = threadIdx.x;
    if (c >= OUT_DIM) return;
    float mean = g_sums[c] / (float)EE;
    float var  = g_sumsq[c] / (float)EE - mean * mean;
    float sc = rsqrtf(var + EPS) * g1[c];
    g_scale1[c] = sc;
    g_shift1[c] = beta1[c] - mean * sc;
}

// ---------------------------------------------------------------
// act_scatter: BN1 apply + sigmoid*softplus gate + red.v4 scatter
// ---------------------------------------------------------------
__global__ __launch_bounds__(256)
void act_scatter_kernel(const int* __restrict__ dst) {
    int idx = blockIdx.x * blockDim.x + threadIdx.x;   // over EE*16
    int e  = idx >> 4;
    int cg = (idx & 15) * 4;
    const __half2* hp = (const __half2*)(g_h + (size_t)e * OUT_DIM);
    float2 f01 = __half22float2(hp[(cg >> 1) + 0]);
    float2 f23 = __half22float2(hp[(cg >> 1) + 1]);
    float2 g01 = __half22float2(hp[(cg >> 1) + 32]);
    float2 g23 = __half22float2(hp[(cg >> 1) + 33]);
    float4 s1 = *(const float4*)(g_scale1 + cg);
    float4 h1 = *(const float4*)(g_shift1 + cg);
    float4 s2 = *(const float4*)(g_scale1 + cg + 64);
    float4 h2 = *(const float4*)(g_shift1 + cg + 64);

    float m0, m1, m2, m3;
    {
        float f = f01.x * s1.x + h1.x, g = g01.x * s2.x + h2.x;
        m0 = (1.f / (1.f + expf(-f))) * softplus_f(g);
        f = f01.y * s1.y + h1.y; g = g01.y * s2.y + h2.y;
        m1 = (1.f / (1.f + expf(-f))) * softplus_f(g);
        f = f23.x * s1.z + h1.z; g = g23.x * s2.z + h2.z;
        m2 = (1.f / (1.f + expf(-f))) * softplus_f(g);
        f = f23.y * s1.w + h1.w; g = g23.y * s2.w + h2.w;
        m3 = (1.f / (1.f + expf(-f))) * softplus_f(g);
    }
    float* ap = g_agg + (size_t)__ldg(dst + e) * 64 + cg;
    asm volatile("red.global.add.v4.f32 [%0], {%1,%2,%3,%4};"
                 :: "l"(ap), "f"(m0), "f"(m1), "f"(m2), "f"(m3) : "memory");
}

// ---------------------------------------------------------------
// BN2 stats + finalize + output
// ---------------------------------------------------------------
__global__ void agg_stats_kernel() {
    __shared__ float sh[4][64], shq[4][64];
    int c  = threadIdx.x & 63;
    int rg = threadIdx.x >> 6;
    int r0 = blockIdx.x * 250;
    float s = 0.f, q = 0.f;
    for (int r = r0 + rg; r < r0 + 250; r += 4) {
        float v = g_agg[r * 64 + c];
        s += v;
        q = fmaf(v, v, q);
    }
    sh[rg][c] = s; shq[rg][c] = q;
    __syncthreads();
    if (threadIdx.x < 64) {
        atomicAdd(&g_s2[c], sh[0][c] + sh[1][c] + sh[2][c] + sh[3][c]);
        atomicAdd(&g_q2[c], shq[0][c] + shq[1][c] + shq[2][c] + shq[3][c]);
    }
}

__global__ void finalize2_kernel(const float* __restrict__ g2,
                                 const float* __restrict__ beta2) {
    int c = threadIdx.x;
    if (c >= OO) return;
    float mean = g_s2[c] / (float)NN;
    float var  = g_q2[c] / (float)NN - mean * mean;
    float sc = rsqrtf(var + EPS) * g2[c];
    g_scale2[c] = sc;
    g_shift2[c] = beta2[c] - mean * sc;
}

__global__ void output_kernel(const float* __restrict__ n_feat,
                              float* __restrict__ out) {
    int idx = blockIdx.x * blockDim.x + threadIdx.x;
    if (idx >= NN * OO) return;
    int c = idx & 63;
    float v = g_agg[idx] * g_scale2[c] + g_shift2[c] + n_feat[idx];
    out[idx] = softplus_f(v);
}

// ---------------------------------------------------------------
extern "C" void kernel_launch(void* const* d_in, const int* in_sizes, int n_in,
                              void* d_out, int out_size) {
    const float* n_feat = (const float*)d_in[0];
    const float* e_feat = (const float*)d_in[1];
    const int*   src    = (const int*)  d_in[2];
    const int*   dst    = (const int*)  d_in[3];
    const float* W      = (const float*)d_in[4];
    const float* b      = (const float*)d_in[5];
    const float* g1     = (const float*)d_in[6];
    const float* beta1  = (const float*)d_in[7];
    const float* g2     = (const float*)d_in[8];
    const float* beta2  = (const float*)d_in[9];
    float* out = (float*)d_out;

    cudaFuncSetAttribute(pass1_kernel, cudaFuncAttributeMaxDynamicSharedMemorySize, SM_TOTAL);

    pre_kernel<<<444, 256>>>(n_feat, W, b);
    pass1_kernel<<<GRID, 512, SM_TOTAL>>>(e_feat, src, dst, W);
    finalize1_kernel<<<1, 128>>>(g1, beta1);
    act_scatter_kernel<<<(EE * 16) / 256, 256>>>(dst);
    agg_stats_kernel<<<200, 256>>>();
    finalize2_kernel<<<1, 64>>>(g2, beta2);
    output_kernel<<<(NN * OO + 255) / 256, 256>>>(n_feat, out);
}